// round 11
// baseline (speedup 1.0000x reference)
#include <cuda_runtime.h>
#include <cuda_fp16.h>
#include <cstdint>

#define SEQ 2048
#define HD  64
#define BM  64
#define BN  64
#define NT  128
#define NTILES (SEQ / BN)
#define BH  32
#define PSC 0.125f
#define QJL 0.01f
#define QSCALE 0.18033688011112042f   // (1/8) * log2(e)

#define CH_SM 80
#define KREG_B (128 * CH_SM)           // 10240
#define BUF_B  (2 * KREG_B)            // 20480
#define NBUF 4
#define SMEM_BYTES (NBUF * BUF_B)      // 81920

__device__ __half2 g_kd2[BH * SEQ * HD / 2];
__device__ __half2 g_vd2[BH * SEQ * HD / 2];

__device__ __forceinline__ float ex2f_(float x) {
    float r; asm("ex2.approx.f32 %0, %1;" : "=f"(r) : "f"(x)); return r;
}
__device__ __forceinline__ uint32_t h2u(__half2 h) { return *reinterpret_cast<uint32_t*>(&h); }

__device__ __forceinline__ void mma_f16(float* d, const uint32_t* a,
                                        uint32_t b0, uint32_t b1) {
    asm volatile(
        "mma.sync.aligned.m16n8k16.row.col.f32.f16.f16.f32 "
        "{%0,%1,%2,%3}, {%4,%5,%6,%7}, {%8,%9}, {%0,%1,%2,%3};"
        : "+f"(d[0]), "+f"(d[1]), "+f"(d[2]), "+f"(d[3])
        : "r"(a[0]), "r"(a[1]), "r"(a[2]), "r"(a[3]), "r"(b0), "r"(b1));
}
__device__ __forceinline__ uint32_t smem_u32(const void* p) {
    uint32_t a;
    asm("{ .reg .u64 t; cvta.to.shared.u64 t, %1; cvt.u32.u64 %0, t; }" : "=r"(a) : "l"(p));
    return a;
}
__device__ __forceinline__ void cp16(uint32_t dst, const void* src) {
    asm volatile("cp.async.cg.shared.global [%0], [%1], 16;" :: "r"(dst), "l"(src));
}

// ---- fused pre-pass (unchanged) ----
#define KSTR2 36
#define VSTRH 72

__global__ void __launch_bounds__(256) deq_kv(
    const float* __restrict__ kp, const float* __restrict__ kq,
    const float* __restrict__ vp, const float* __restrict__ vq)
{
    __shared__ __half2 sK2[64 * KSTR2];
    __shared__ __half  sVt[64 * VSTRH];

    const int tid = threadIdx.x;
    const size_t rowbase = (size_t)blockIdx.x * (64 * HD);

    #pragma unroll
    for (int it = 0; it < 4; ++it) {
        int idx = tid + it * 256;
        int r = idx >> 4, c4 = idx & 15;
        size_t gq = rowbase + (size_t)r * HD + c4 * 4;

        float4 a = *reinterpret_cast<const float4*>(kp + gq);
        float4 b = *reinterpret_cast<const float4*>(kq + gq);
        __half2 h0 = __floats2half2_rn(a.x * PSC + b.x * QJL, a.y * PSC + b.y * QJL);
        __half2 h1 = __floats2half2_rn(a.z * PSC + b.z * QJL, a.w * PSC + b.w * QJL);
        *reinterpret_cast<uint2*>(&sK2[r * KSTR2 + c4 * 2]) =
            make_uint2(h2u(h0), h2u(h1));

        a = *reinterpret_cast<const float4*>(vp + gq);
        b = *reinterpret_cast<const float4*>(vq + gq);
        sVt[(c4 * 4 + 0) * VSTRH + r] = __float2half_rn(a.x * PSC + b.x * QJL);
        sVt[(c4 * 4 + 1) * VSTRH + r] = __float2half_rn(a.y * PSC + b.y * QJL);
        sVt[(c4 * 4 + 2) * VSTRH + r] = __float2half_rn(a.z * PSC + b.z * QJL);
        sVt[(c4 * 4 + 3) * VSTRH + r] = __float2half_rn(a.w * PSC + b.w * QJL);
    }
    __syncthreads();

    const int c   = tid & 127;
    const int t   = c & 3;
    const int g   = (c >> 2) & 7;
    const int kc2 = c >> 5;

    uint32_t w[16];
    char* dst;
    if (tid < 128) {
        #pragma unroll
        for (int nt = 0; nt < 8; ++nt) {
            int rw = (nt * 8 + g) * KSTR2 + kc2 * 8 + t;
            w[2 * nt]     = h2u(sK2[rw]);
            w[2 * nt + 1] = h2u(sK2[rw + 4]);
        }
        dst = reinterpret_cast<char*>(g_kd2) + (size_t)blockIdx.x * 8192 + c * 64;
    } else {
        #pragma unroll
        for (int dt = 0; dt < 8; ++dt) {
            int n = dt * 8 + g;
            int a0 = n * VSTRH + kc2 * 16 + 2 * t;
            w[2 * dt]     = *reinterpret_cast<uint32_t*>(&sVt[a0]);
            w[2 * dt + 1] = *reinterpret_cast<uint32_t*>(&sVt[a0 + 8]);
        }
        dst = reinterpret_cast<char*>(g_vd2) + (size_t)blockIdx.x * 8192 + c * 64;
    }
    #pragma unroll
    for (int u4 = 0; u4 < 4; ++u4)
        *reinterpret_cast<uint4*>(dst + u4 * 16) =
            make_uint4(w[4 * u4], w[4 * u4 + 1], w[4 * u4 + 2], w[4 * u4 + 3]);
}

// ---- attention: tile-interleaved software pipeline, 4-stage ring ----
#define ISSUE8(TILE, BUFI) do {                                              \
    const char* _ks = kgm + (size_t)(TILE) * 8192;                           \
    const char* _vs = vgm + (size_t)(TILE) * 8192;                           \
    uint32_t _bb = sb + (uint32_t)(BUFI) * BUF_B;                            \
    _Pragma("unroll")                                                        \
    for (int _it = 0; _it < 4; ++_it) {                                      \
        int _part = tid + _it * NT;                                          \
        uint32_t _doff = (_part >> 2) * CH_SM + (_part & 3) * 16;            \
        cp16(_bb + _doff, _ks + _part * 16);                                 \
        cp16(_bb + KREG_B + _doff, _vs + _part * 16);                        \
    }                                                                        \
} while (0)

#define BODY(TL, SC, SN, DOQK) do {                                          \
    __syncthreads();                                                         \
    if ((TL) + 3 < NTILES) ISSUE8((TL) + 3, ((TL) + 3) & 3);                 \
    asm volatile("cp.async.commit_group;" ::: "memory");                     \
    asm volatile("cp.async.wait_group 1;" ::: "memory");                     \
    if (DOQK) {                                                              \
        _Pragma("unroll")                                                    \
        for (int _i = 0; _i < 8; ++_i) {                                     \
            _Pragma("unroll")                                                \
            for (int _j = 0; _j < 4; ++_j) SN[_i][_j] = 0.f;                 \
        }                                                                    \
    }                                                                        \
    _Pragma("unroll")                                                        \
    for (int kc2 = 0; kc2 < 4; ++kc2) {                                      \
        if (DOQK) {                                                          \
            const char* ca = dsm + (((TL) + 1) & 3) * BUF_B                  \
                           + kc2 * 32 * CH_SM + mych;                        \
            uint4 B0 = *reinterpret_cast<const uint4*>(ca);                  \
            uint4 B1 = *reinterpret_cast<const uint4*>(ca + 16);             \
            uint4 B2 = *reinterpret_cast<const uint4*>(ca + 32);             \
            uint4 B3 = *reinterpret_cast<const uint4*>(ca + 48);             \
            mma_f16(SN[0], qa[kc2], B0.x, B0.y);                             \
            mma_f16(SN[1], qa[kc2], B0.z, B0.w);                             \
            mma_f16(SN[2], qa[kc2], B1.x, B1.y);                             \
            mma_f16(SN[3], qa[kc2], B1.z, B1.w);                             \
            mma_f16(SN[4], qa[kc2], B2.x, B2.y);                             \
            mma_f16(SN[5], qa[kc2], B2.z, B2.w);                             \
            mma_f16(SN[6], qa[kc2], B3.x, B3.y);                             \
            mma_f16(SN[7], qa[kc2], B3.z, B3.w);                             \
        }                                                                    \
        float p00 = ex2f_(SC[2 * kc2][0]);                                   \
        float p01 = ex2f_(SC[2 * kc2][1]);                                   \
        float p02 = ex2f_(SC[2 * kc2][2]);                                   \
        float p03 = ex2f_(SC[2 * kc2][3]);                                   \
        float p10 = ex2f_(SC[2 * kc2 + 1][0]);                               \
        float p11 = ex2f_(SC[2 * kc2 + 1][1]);                               \
        float p12 = ex2f_(SC[2 * kc2 + 1][2]);                               \
        float p13 = ex2f_(SC[2 * kc2 + 1][3]);                               \
        rsum0 += (p00 + p01) + (p10 + p11);                                  \
        rsum1 += (p02 + p03) + (p12 + p13);                                  \
        uint32_t pa[4];                                                      \
        pa[0] = h2u(__floats2half2_rn(p00, p01));                            \
        pa[1] = h2u(__floats2half2_rn(p02, p03));                            \
        pa[2] = h2u(__floats2half2_rn(p10, p11));                            \
        pa[3] = h2u(__floats2half2_rn(p12, p13));                            \
        const char* cv = dsm + ((TL) & 3) * BUF_B + KREG_B                   \
                       + kc2 * 32 * CH_SM + mych;                            \
        uint4 V0 = *reinterpret_cast<const uint4*>(cv);                      \
        uint4 V1 = *reinterpret_cast<const uint4*>(cv + 16);                 \
        uint4 V2 = *reinterpret_cast<const uint4*>(cv + 32);                 \
        uint4 V3 = *reinterpret_cast<const uint4*>(cv + 48);                 \
        mma_f16(o[0], pa, V0.x, V0.y);                                       \
        mma_f16(o[1], pa, V0.z, V0.w);                                       \
        mma_f16(o[2], pa, V1.x, V1.y);                                       \
        mma_f16(o[3], pa, V1.z, V1.w);                                       \
        mma_f16(o[4], pa, V2.x, V2.y);                                       \
        mma_f16(o[5], pa, V2.z, V2.w);                                       \
        mma_f16(o[6], pa, V3.x, V3.y);                                       \
        mma_f16(o[7], pa, V3.z, V3.w);                                       \
    }                                                                        \
} while (0)

__global__ void __launch_bounds__(NT, 2) tq_attn_mma(
    const float* __restrict__ q, float* __restrict__ out)
{
    extern __shared__ char dsm[];
    const uint32_t sb = smem_u32(dsm);

    const int tid  = threadIdx.x;
    const int wid  = tid >> 5;
    const int lane = tid & 31;
    const int g    = lane >> 2;
    const int t    = lane & 3;
    const int wrow = wid * 16;

    const int    m0   = blockIdx.x * BM;
    const int    bh   = blockIdx.y;
    const size_t base = (size_t)bh * (size_t)(SEQ * HD);

    // ---- stage Q in buffer region, build fp16 A-fragments ----
    {
        float* sQ = reinterpret_cast<float*>(dsm);
        #pragma unroll
        for (int it = 0; it < 8; ++it) {
            int idx = tid + it * NT;
            int r = idx >> 4, c4 = idx & 15;
            float4 v = *reinterpret_cast<const float4*>(
                q + base + (size_t)(m0 + r) * HD + c4 * 4);
            *reinterpret_cast<float4*>(&sQ[r * HD + c4 * 4]) = v;
        }
    }
    __syncthreads();
    uint32_t qa[4][4];
    {
        const float* q0 = reinterpret_cast<float*>(dsm) + (wrow + g) * HD + 2 * t;
        const float* q8 = q0 + 8 * HD;
        #pragma unroll
        for (int kc2 = 0; kc2 < 4; ++kc2) {
            int c = kc2 * 16;
            qa[kc2][0] = h2u(__floats2half2_rn(QSCALE * q0[c],     QSCALE * q0[c + 1]));
            qa[kc2][1] = h2u(__floats2half2_rn(QSCALE * q8[c],     QSCALE * q8[c + 1]));
            qa[kc2][2] = h2u(__floats2half2_rn(QSCALE * q0[c + 8], QSCALE * q0[c + 9]));
            qa[kc2][3] = h2u(__floats2half2_rn(QSCALE * q8[c + 8], QSCALE * q8[c + 9]));
        }
    }
    __syncthreads();

    const char* kgm = reinterpret_cast<const char*>(g_kd2) + (size_t)bh * 32 * 8192;
    const char* vgm = reinterpret_cast<const char*>(g_vd2) + (size_t)bh * 32 * 8192;
    const uint32_t mych = (g * 4 + t) * CH_SM;

    // ---- prologue: 3 tiles in flight, then QK(0) ----
    ISSUE8(0, 0);
    asm volatile("cp.async.commit_group;" ::: "memory");
    ISSUE8(1, 1);
    asm volatile("cp.async.commit_group;" ::: "memory");
    ISSUE8(2, 2);
    asm volatile("cp.async.commit_group;" ::: "memory");
    asm volatile("cp.async.wait_group 1;" ::: "memory");   // groups 0,1 done
    __syncthreads();

    float sA[8][4], sB[8][4];
    #pragma unroll
    for (int i = 0; i < 8; ++i)
        #pragma unroll
        for (int j = 0; j < 4; ++j) sA[i][j] = 0.f;
    #pragma unroll
    for (int kc2 = 0; kc2 < 4; ++kc2) {
        const char* ca = dsm + kc2 * 32 * CH_SM + mych;    // buf 0
        uint4 B0 = *reinterpret_cast<const uint4*>(ca);
        uint4 B1 = *reinterpret_cast<const uint4*>(ca + 16);
        uint4 B2 = *reinterpret_cast<const uint4*>(ca + 32);
        uint4 B3 = *reinterpret_cast<const uint4*>(ca + 48);
        mma_f16(sA[0], qa[kc2], B0.x, B0.y);
        mma_f16(sA[1], qa[kc2], B0.z, B0.w);
        mma_f16(sA[2], qa[kc2], B1.x, B1.y);
        mma_f16(sA[3], qa[kc2], B1.z, B1.w);
        mma_f16(sA[4], qa[kc2], B2.x, B2.y);
        mma_f16(sA[5], qa[kc2], B2.z, B2.w);
        mma_f16(sA[6], qa[kc2], B3.x, B3.y);
        mma_f16(sA[7], qa[kc2], B3.z, B3.w);
    }

    float o[8][4];
    #pragma unroll
    for (int i = 0; i < 8; ++i)
        #pragma unroll
        for (int j = 0; j < 4; ++j) o[i][j] = 0.f;
    float rsum0 = 0.f, rsum1 = 0.f;

    // ---- main loop: softmax+PV(t) interleaved with QK(t+1) ----
    for (int tl = 0; tl < NTILES; tl += 2) {
        BODY(tl, sA, sB, true);
        BODY(tl + 1, sB, sA, (tl + 2 < NTILES));
    }

    // ---- epilogue ----
    rsum0 += __shfl_xor_sync(0xffffffffu, rsum0, 1);
    rsum0 += __shfl_xor_sync(0xffffffffu, rsum0, 2);
    rsum1 += __shfl_xor_sync(0xffffffffu, rsum1, 1);
    rsum1 += __shfl_xor_sync(0xffffffffu, rsum1, 2);
    const float inv0 = 1.0f / rsum0;
    const float inv1 = 1.0f / rsum1;

    const size_t row0 = base + (size_t)(m0 + wrow + g) * HD;
    const size_t row1 = row0 + 8 * HD;
    #pragma unroll
    for (int dt = 0; dt < 8; ++dt) {
        float2 r0 = make_float2(o[dt][0] * inv0, o[dt][1] * inv0);
        float2 r1 = make_float2(o[dt][2] * inv1, o[dt][3] * inv1);
        *reinterpret_cast<float2*>(out + row0 + dt * 8 + 2 * t) = r0;
        *reinterpret_cast<float2*>(out + row1 + dt * 8 + 2 * t) = r1;
    }
}

extern "C" void kernel_launch(void* const* d_in, const int* in_sizes, int n_in,
                              void* d_out, int out_size)
{
    const float* q  = (const float*)d_in[0];
    const float* kp = (const float*)d_in[1];
    const float* kq = (const float*)d_in[2];
    const float* vp = (const float*)d_in[3];
    const float* vq = (const float*)d_in[4];
    float* out = (float*)d_out;

    static int cfg_done = 0;
    if (!cfg_done) {
        cudaFuncSetAttribute(tq_attn_mma,
                             cudaFuncAttributeMaxDynamicSharedMemorySize, SMEM_BYTES);
        cfg_done = 1;
    }

    deq_kv<<<BH * NTILES, 256>>>(kp, kq, vp, vq);

    dim3 grid(SEQ / BM, BH);
    tq_attn_mma<<<grid, NT, SMEM_BYTES>>>(q, out);
}

// round 12
// speedup vs baseline: 1.1779x; 1.1779x over previous
#include <cuda_runtime.h>
#include <cuda_fp16.h>
#include <cstdint>

#define SEQ 2048
#define HD  64
#define BM  64
#define BN  64
#define NT  128
#define NTILES (SEQ / BN)
#define BH  32
#define PSC 0.125f
#define QJL 0.01f
#define QSCALE 0.18033688011112042f   // (1/8) * log2(e)

#define CH_SM 80
#define KREG_B (128 * CH_SM)           // 10240
#define BUF_B  (2 * KREG_B)            // 20480
#define SMEM_BYTES (2 * BUF_B)         // 40960

#define ONESH2 0x3C003C00u             // half2(1.0, 1.0)

__device__ __half2 g_kd2[BH * SEQ * HD / 2];
__device__ __half2 g_vd2[BH * SEQ * HD / 2];

__device__ __forceinline__ uint32_t h2u(__half2 h) { return *reinterpret_cast<uint32_t*>(&h); }

__device__ __forceinline__ uint32_t ex2h2(uint32_t x) {   // elementwise 2^x on half2
    uint32_t r; asm("ex2.approx.f16x2 %0, %1;" : "=r"(r) : "r"(x)); return r;
}

__device__ __forceinline__ void mma_f16(float* d, const uint32_t* a,
                                        uint32_t b0, uint32_t b1) {
    asm volatile(
        "mma.sync.aligned.m16n8k16.row.col.f32.f16.f16.f32 "
        "{%0,%1,%2,%3}, {%4,%5,%6,%7}, {%8,%9}, {%0,%1,%2,%3};"
        : "+f"(d[0]), "+f"(d[1]), "+f"(d[2]), "+f"(d[3])
        : "r"(a[0]), "r"(a[1]), "r"(a[2]), "r"(a[3]), "r"(b0), "r"(b1));
}
__device__ __forceinline__ uint32_t smem_u32(const void* p) {
    uint32_t a;
    asm("{ .reg .u64 t; cvta.to.shared.u64 t, %1; cvt.u32.u64 %0, t; }" : "=r"(a) : "l"(p));
    return a;
}
__device__ __forceinline__ void cp16(uint32_t dst, const void* src) {
    asm volatile("cp.async.cg.shared.global [%0], [%1], 16;" :: "r"(dst), "l"(src));
}

// ---- fused pre-pass (unchanged from R9) ----
#define KSTR2 36
#define VSTRH 72

__global__ void __launch_bounds__(256) deq_kv(
    const float* __restrict__ kp, const float* __restrict__ kq,
    const float* __restrict__ vp, const float* __restrict__ vq)
{
    __shared__ __half2 sK2[64 * KSTR2];
    __shared__ __half  sVt[64 * VSTRH];

    const int tid = threadIdx.x;
    const size_t rowbase = (size_t)blockIdx.x * (64 * HD);

    #pragma unroll
    for (int it = 0; it < 4; ++it) {
        int idx = tid + it * 256;
        int r = idx >> 4, c4 = idx & 15;
        size_t gq = rowbase + (size_t)r * HD + c4 * 4;

        float4 a = *reinterpret_cast<const float4*>(kp + gq);
        float4 b = *reinterpret_cast<const float4*>(kq + gq);
        __half2 h0 = __floats2half2_rn(a.x * PSC + b.x * QJL, a.y * PSC + b.y * QJL);
        __half2 h1 = __floats2half2_rn(a.z * PSC + b.z * QJL, a.w * PSC + b.w * QJL);
        *reinterpret_cast<uint2*>(&sK2[r * KSTR2 + c4 * 2]) =
            make_uint2(h2u(h0), h2u(h1));

        a = *reinterpret_cast<const float4*>(vp + gq);
        b = *reinterpret_cast<const float4*>(vq + gq);
        sVt[(c4 * 4 + 0) * VSTRH + r] = __float2half_rn(a.x * PSC + b.x * QJL);
        sVt[(c4 * 4 + 1) * VSTRH + r] = __float2half_rn(a.y * PSC + b.y * QJL);
        sVt[(c4 * 4 + 2) * VSTRH + r] = __float2half_rn(a.z * PSC + b.z * QJL);
        sVt[(c4 * 4 + 3) * VSTRH + r] = __float2half_rn(a.w * PSC + b.w * QJL);
    }
    __syncthreads();

    const int c   = tid & 127;
    const int t   = c & 3;
    const int g   = (c >> 2) & 7;
    const int kc2 = c >> 5;

    uint32_t w[16];
    char* dst;
    if (tid < 128) {
        #pragma unroll
        for (int nt = 0; nt < 8; ++nt) {
            int rw = (nt * 8 + g) * KSTR2 + kc2 * 8 + t;
            w[2 * nt]     = h2u(sK2[rw]);
            w[2 * nt + 1] = h2u(sK2[rw + 4]);
        }
        dst = reinterpret_cast<char*>(g_kd2) + (size_t)blockIdx.x * 8192 + c * 64;
    } else {
        #pragma unroll
        for (int dt = 0; dt < 8; ++dt) {
            int n = dt * 8 + g;
            int a0 = n * VSTRH + kc2 * 16 + 2 * t;
            w[2 * dt]     = *reinterpret_cast<uint32_t*>(&sVt[a0]);
            w[2 * dt + 1] = *reinterpret_cast<uint32_t*>(&sVt[a0 + 8]);
        }
        dst = reinterpret_cast<char*>(g_vd2) + (size_t)blockIdx.x * 8192 + c * 64;
    }
    #pragma unroll
    for (int u4 = 0; u4 < 4; ++u4)
        *reinterpret_cast<uint4*>(dst + u4 * 16) =
            make_uint4(w[4 * u4], w[4 * u4 + 1], w[4 * u4 + 2], w[4 * u4 + 3]);
}

// ---- attention (R9 skeleton + f16x2 ex2 + rsum-via-ones-MMA) ----
__global__ void __launch_bounds__(NT, 4) tq_attn_mma(
    const float* __restrict__ q, float* __restrict__ out)
{
    extern __shared__ char dsm[];
    const uint32_t sb = smem_u32(dsm);

    const int tid  = threadIdx.x;
    const int wid  = tid >> 5;
    const int lane = tid & 31;
    const int g    = lane >> 2;
    const int t    = lane & 3;
    const int wrow = wid * 16;

    const int    m0   = blockIdx.x * BM;
    const int    bh   = blockIdx.y;
    const size_t base = (size_t)bh * (size_t)(SEQ * HD);

    {
        float* sQ = reinterpret_cast<float*>(dsm);
        #pragma unroll
        for (int it = 0; it < 8; ++it) {
            int idx = tid + it * NT;
            int r = idx >> 4, c4 = idx & 15;
            float4 v = *reinterpret_cast<const float4*>(
                q + base + (size_t)(m0 + r) * HD + c4 * 4);
            *reinterpret_cast<float4*>(&sQ[r * HD + c4 * 4]) = v;
        }
    }
    __syncthreads();
    uint32_t qa[4][4];
    {
        const float* q0 = reinterpret_cast<float*>(dsm) + (wrow + g) * HD + 2 * t;
        const float* q8 = q0 + 8 * HD;
        #pragma unroll
        for (int kc2 = 0; kc2 < 4; ++kc2) {
            int c = kc2 * 16;
            qa[kc2][0] = h2u(__floats2half2_rn(QSCALE * q0[c],     QSCALE * q0[c + 1]));
            qa[kc2][1] = h2u(__floats2half2_rn(QSCALE * q8[c],     QSCALE * q8[c + 1]));
            qa[kc2][2] = h2u(__floats2half2_rn(QSCALE * q0[c + 8], QSCALE * q0[c + 9]));
            qa[kc2][3] = h2u(__floats2half2_rn(QSCALE * q8[c + 8], QSCALE * q8[c + 9]));
        }
    }
    __syncthreads();

    const char* kgm = reinterpret_cast<const char*>(g_kd2) + (size_t)bh * 32 * 8192;
    const char* vgm = reinterpret_cast<const char*>(g_vd2) + (size_t)bh * 32 * 8192;

    #pragma unroll
    for (int it = 0; it < 4; ++it) {
        int part = tid + it * NT;
        uint32_t doff = (part >> 2) * CH_SM + (part & 3) * 16;
        cp16(sb + doff, kgm + part * 16);
        cp16(sb + KREG_B + doff, vgm + part * 16);
    }
    asm volatile("cp.async.commit_group;" ::: "memory");

    float o[8][4];
    #pragma unroll
    for (int i = 0; i < 8; ++i)
        #pragma unroll
        for (int j = 0; j < 4; ++j) o[i][j] = 0.f;
    float o8[4] = {0.f, 0.f, 0.f, 0.f};          // rsum accumulator (P @ ones)

    const uint32_t mych = (g * 4 + t) * CH_SM;

    for (int tl = 0; tl < NTILES; ++tl) {
        if (tl + 1 < NTILES) {
            const uint32_t nb = sb + ((tl + 1) & 1) * BUF_B;
            const char* ks = kgm + (size_t)(tl + 1) * 8192;
            const char* vs = vgm + (size_t)(tl + 1) * 8192;
            #pragma unroll
            for (int it = 0; it < 4; ++it) {
                int part = tid + it * NT;
                uint32_t doff = (part >> 2) * CH_SM + (part & 3) * 16;
                cp16(nb + doff, ks + part * 16);
                cp16(nb + KREG_B + doff, vs + part * 16);
            }
            asm volatile("cp.async.commit_group;" ::: "memory");
            asm volatile("cp.async.wait_group 1;" ::: "memory");
        } else {
            asm volatile("cp.async.wait_group 0;" ::: "memory");
        }
        __syncthreads();

        // ---- S = Q K^T ----
        float s[8][4];
        #pragma unroll
        for (int i = 0; i < 8; ++i)
            #pragma unroll
            for (int j = 0; j < 4; ++j) s[i][j] = 0.f;

        #pragma unroll
        for (int kc2 = 0; kc2 < 4; ++kc2) {
            const char* ca = dsm + (tl & 1) * BUF_B + kc2 * 32 * CH_SM + mych;
            uint4 B0 = *reinterpret_cast<const uint4*>(ca);
            uint4 B1 = *reinterpret_cast<const uint4*>(ca + 16);
            uint4 B2 = *reinterpret_cast<const uint4*>(ca + 32);
            uint4 B3 = *reinterpret_cast<const uint4*>(ca + 48);
            mma_f16(s[0], qa[kc2], B0.x, B0.y);
            mma_f16(s[1], qa[kc2], B0.z, B0.w);
            mma_f16(s[2], qa[kc2], B1.x, B1.y);
            mma_f16(s[3], qa[kc2], B1.z, B1.w);
            mma_f16(s[4], qa[kc2], B2.x, B2.y);
            mma_f16(s[5], qa[kc2], B2.z, B2.w);
            mma_f16(s[6], qa[kc2], B3.x, B3.y);
            mma_f16(s[7], qa[kc2], B3.z, B3.w);
        }

        // ---- fused softmax (f16x2 ex2) + rsum-MMA + PV per k-chunk ----
        #pragma unroll
        for (int kc2 = 0; kc2 < 4; ++kc2) {
            uint32_t pa[4];
            pa[0] = ex2h2(h2u(__floats2half2_rn(s[2 * kc2][0],     s[2 * kc2][1])));
            pa[1] = ex2h2(h2u(__floats2half2_rn(s[2 * kc2][2],     s[2 * kc2][3])));
            pa[2] = ex2h2(h2u(__floats2half2_rn(s[2 * kc2 + 1][0], s[2 * kc2 + 1][1])));
            pa[3] = ex2h2(h2u(__floats2half2_rn(s[2 * kc2 + 1][2], s[2 * kc2 + 1][3])));

            mma_f16(o8, pa, ONESH2, ONESH2);   // row sums (all cols identical)

            const char* cv = dsm + (tl & 1) * BUF_B + KREG_B + kc2 * 32 * CH_SM + mych;
            uint4 V0 = *reinterpret_cast<const uint4*>(cv);
            uint4 V1 = *reinterpret_cast<const uint4*>(cv + 16);
            uint4 V2 = *reinterpret_cast<const uint4*>(cv + 32);
            uint4 V3 = *reinterpret_cast<const uint4*>(cv + 48);
            mma_f16(o[0], pa, V0.x, V0.y);
            mma_f16(o[1], pa, V0.z, V0.w);
            mma_f16(o[2], pa, V1.x, V1.y);
            mma_f16(o[3], pa, V1.z, V1.w);
            mma_f16(o[4], pa, V2.x, V2.y);
            mma_f16(o[5], pa, V2.z, V2.w);
            mma_f16(o[6], pa, V3.x, V3.y);
            mma_f16(o[7], pa, V3.z, V3.w);
        }
        __syncthreads();
    }

    // ---- epilogue: rsum comes straight from o8 (no shuffles) ----
    const float inv0 = 1.0f / o8[0];
    const float inv1 = 1.0f / o8[2];

    const size_t row0 = base + (size_t)(m0 + wrow + g) * HD;
    const size_t row1 = row0 + 8 * HD;
    #pragma unroll
    for (int dt = 0; dt < 8; ++dt) {
        float2 r0 = make_float2(o[dt][0] * inv0, o[dt][1] * inv0);
        float2 r1 = make_float2(o[dt][2] * inv1, o[dt][3] * inv1);
        *reinterpret_cast<float2*>(out + row0 + dt * 8 + 2 * t) = r0;
        *reinterpret_cast<float2*>(out + row1 + dt * 8 + 2 * t) = r1;
    }
}

extern "C" void kernel_launch(void* const* d_in, const int* in_sizes, int n_in,
                              void* d_out, int out_size)
{
    const float* q  = (const float*)d_in[0];
    const float* kp = (const float*)d_in[1];
    const float* kq = (const float*)d_in[2];
    const float* vp = (const float*)d_in[3];
    const float* vq = (const float*)d_in[4];
    float* out = (float*)d_out;

    static int cfg_done = 0;
    if (!cfg_done) {
        cudaFuncSetAttribute(tq_attn_mma,
                             cudaFuncAttributeMaxDynamicSharedMemorySize, SMEM_BYTES);
        cfg_done = 1;
    }

    deq_kv<<<BH * NTILES, 256>>>(kp, kq, vp, vq);

    dim3 grid(SEQ / BM, BH);
    tq_attn_mma<<<grid, NT, SMEM_BYTES>>>(q, out);
}

// round 13
// speedup vs baseline: 1.4839x; 1.2598x over previous
#include <cuda_runtime.h>
#include <cuda_fp16.h>
#include <cstdint>

#define SEQ 2048
#define HD  64
#define BM  64
#define BN  64
#define NT  128
#define NTILES (SEQ / BN)
#define BH  32
#define PSC 0.125f
#define QJL 0.01f
#define QSCALE 0.18033688011112042f   // (1/8) * log2(e)

#define TILE_B 8192                    // one K or V tile: 64 rows x 128B, row-major swizzled
#define BUF_B  (2 * TILE_B)            // K + V per stage
#define SMEM_BYTES (2 * BUF_B)         // 32768, double-buffered

// 16 MB scratch: plain row-major dequantized fp16 K and V
__device__ __half g_kd[BH * SEQ * HD];
__device__ __half g_vd[BH * SEQ * HD];

__device__ __forceinline__ uint32_t h2u(__half2 h) { return *reinterpret_cast<uint32_t*>(&h); }
__device__ __forceinline__ __half2 u2h(uint32_t u) { return *reinterpret_cast<__half2*>(&u); }

__device__ __forceinline__ uint32_t ex2h2(uint32_t x) {
    uint32_t r; asm("ex2.approx.f16x2 %0, %1;" : "=r"(r) : "r"(x)); return r;
}
__device__ __forceinline__ void mma_f16(float* d, const uint32_t* a,
                                        uint32_t b0, uint32_t b1) {
    asm volatile(
        "mma.sync.aligned.m16n8k16.row.col.f32.f16.f16.f32 "
        "{%0,%1,%2,%3}, {%4,%5,%6,%7}, {%8,%9}, {%0,%1,%2,%3};"
        : "+f"(d[0]), "+f"(d[1]), "+f"(d[2]), "+f"(d[3])
        : "r"(a[0]), "r"(a[1]), "r"(a[2]), "r"(a[3]), "r"(b0), "r"(b1));
}
__device__ __forceinline__ void ldsm4(uint32_t& r0, uint32_t& r1, uint32_t& r2,
                                      uint32_t& r3, uint32_t a) {
    asm volatile("ldmatrix.sync.aligned.m8n8.x4.shared.b16 {%0,%1,%2,%3}, [%4];"
                 : "=r"(r0), "=r"(r1), "=r"(r2), "=r"(r3) : "r"(a));
}
__device__ __forceinline__ void ldsm4t(uint32_t& r0, uint32_t& r1, uint32_t& r2,
                                       uint32_t& r3, uint32_t a) {
    asm volatile("ldmatrix.sync.aligned.m8n8.x4.trans.shared.b16 {%0,%1,%2,%3}, [%4];"
                 : "=r"(r0), "=r"(r1), "=r"(r2), "=r"(r3) : "r"(a));
}
__device__ __forceinline__ uint32_t smem_u32(const void* p) {
    uint32_t a;
    asm("{ .reg .u64 t; cvta.to.shared.u64 t, %1; cvt.u32.u64 %0, t; }" : "=r"(a) : "l"(p));
    return a;
}
__device__ __forceinline__ void cp16(uint32_t dst, const void* src) {
    asm volatile("cp.async.cg.shared.global [%0], [%1], 16;" :: "r"(dst), "l"(src));
}

// ---- pre-pass: pure streaming dequant, row-major fp16 out ----
__global__ void __launch_bounds__(256) deq_kv(
    const float* __restrict__ kp, const float* __restrict__ kq,
    const float* __restrict__ vp, const float* __restrict__ vq)
{
    size_t i = ((size_t)blockIdx.x * 256 + threadIdx.x) * 8;   // 8 elems per thread

    float4 a0 = *reinterpret_cast<const float4*>(kp + i);
    float4 a1 = *reinterpret_cast<const float4*>(kp + i + 4);
    float4 b0 = *reinterpret_cast<const float4*>(kq + i);
    float4 b1 = *reinterpret_cast<const float4*>(kq + i + 4);
    uint4 w;
    w.x = h2u(__floats2half2_rn(a0.x * PSC + b0.x * QJL, a0.y * PSC + b0.y * QJL));
    w.y = h2u(__floats2half2_rn(a0.z * PSC + b0.z * QJL, a0.w * PSC + b0.w * QJL));
    w.z = h2u(__floats2half2_rn(a1.x * PSC + b1.x * QJL, a1.y * PSC + b1.y * QJL));
    w.w = h2u(__floats2half2_rn(a1.z * PSC + b1.z * QJL, a1.w * PSC + b1.w * QJL));
    *reinterpret_cast<uint4*>(g_kd + i) = w;

    a0 = *reinterpret_cast<const float4*>(vp + i);
    a1 = *reinterpret_cast<const float4*>(vp + i + 4);
    b0 = *reinterpret_cast<const float4*>(vq + i);
    b1 = *reinterpret_cast<const float4*>(vq + i + 4);
    w.x = h2u(__floats2half2_rn(a0.x * PSC + b0.x * QJL, a0.y * PSC + b0.y * QJL));
    w.y = h2u(__floats2half2_rn(a0.z * PSC + b0.z * QJL, a0.w * PSC + b0.w * QJL));
    w.z = h2u(__floats2half2_rn(a1.x * PSC + b1.x * QJL, a1.y * PSC + b1.y * QJL));
    w.w = h2u(__floats2half2_rn(a1.z * PSC + b1.z * QJL, a1.w * PSC + b1.w * QJL));
    *reinterpret_cast<uint4*>(g_vd + i) = w;
}

// ---- attention: ldmatrix fragments from swizzled row-major tiles ----
__global__ void __launch_bounds__(NT, 4) tq_attn_mma(
    const float* __restrict__ q, float* __restrict__ out)
{
    extern __shared__ char dsm[];
    const uint32_t sb = smem_u32(dsm);

    const int tid  = threadIdx.x;
    const int wid  = tid >> 5;
    const int lane = tid & 31;
    const int g    = lane >> 2;
    const int t    = lane & 3;
    const int wrow = wid * 16;

    const int    m0   = blockIdx.x * BM;
    const int    bh   = blockIdx.y;
    const size_t base = (size_t)bh * (size_t)(SEQ * HD);

    // ---- stage Q (fp32) in buffer region, build fp16 A-fragments ----
    {
        float* sQ = reinterpret_cast<float*>(dsm);   // 16 KB < 32 KB
        #pragma unroll
        for (int it = 0; it < 8; ++it) {
            int idx = tid + it * NT;
            int r = idx >> 4, c4 = idx & 15;
            float4 v = *reinterpret_cast<const float4*>(
                q + base + (size_t)(m0 + r) * HD + c4 * 4);
            *reinterpret_cast<float4*>(&sQ[r * HD + c4 * 4]) = v;
        }
    }
    __syncthreads();
    uint32_t qa[4][4];
    {
        const float* q0 = reinterpret_cast<float*>(dsm) + (wrow + g) * HD + 2 * t;
        const float* q8 = q0 + 8 * HD;
        #pragma unroll
        for (int kc2 = 0; kc2 < 4; ++kc2) {
            int c = kc2 * 16;
            qa[kc2][0] = h2u(__floats2half2_rn(QSCALE * q0[c],     QSCALE * q0[c + 1]));
            qa[kc2][1] = h2u(__floats2half2_rn(QSCALE * q8[c],     QSCALE * q8[c + 1]));
            qa[kc2][2] = h2u(__floats2half2_rn(QSCALE * q0[c + 8], QSCALE * q0[c + 9]));
            qa[kc2][3] = h2u(__floats2half2_rn(QSCALE * q8[c + 8], QSCALE * q8[c + 9]));
        }
    }
    __syncthreads();

    const char* kgm = reinterpret_cast<const char*>(g_kd) + (size_t)bh * SEQ * HD * 2;
    const char* vgm = reinterpret_cast<const char*>(g_vd) + (size_t)bh * SEQ * HD * 2;

    // ---- prologue: async-load tile 0 (row-major -> swizzled smem) ----
    #pragma unroll
    for (int it = 0; it < 4; ++it) {
        int part = tid + it * NT;                 // 0..511
        uint32_t r = part >> 3, c = part & 7;
        uint32_t woff = r * 128 + ((c ^ (r & 7)) << 4);
        cp16(sb + woff, kgm + part * 16);
        cp16(sb + TILE_B + woff, vgm + part * 16);
    }
    asm volatile("cp.async.commit_group;" ::: "memory");

    // per-lane ldmatrix address components
    const uint32_t l7     = lane & 7;
    const uint32_t krbase = ((((uint32_t)lane >> 4) & 1) * 8 + l7) * 128;
    const uint32_t kcbit  = ((uint32_t)lane >> 3) & 1;
    const uint32_t vrbase = ((((uint32_t)lane >> 3) & 1) * 8 + l7) * 128;
    const uint32_t vcbit  = ((uint32_t)lane >> 4) & 1;

    float o[8][4];
    #pragma unroll
    for (int i = 0; i < 8; ++i)
        #pragma unroll
        for (int j = 0; j < 4; ++j) o[i][j] = 0.f;
    float rsum0 = 0.f, rsum1 = 0.f;

    for (int tl = 0; tl < NTILES; ++tl) {
        if (tl + 1 < NTILES) {
            const uint32_t nb = sb + ((tl + 1) & 1) * BUF_B;
            const char* ks = kgm + (size_t)(tl + 1) * TILE_B;
            const char* vs = vgm + (size_t)(tl + 1) * TILE_B;
            #pragma unroll
            for (int it = 0; it < 4; ++it) {
                int part = tid + it * NT;
                uint32_t r = part >> 3, c = part & 7;
                uint32_t woff = r * 128 + ((c ^ (r & 7)) << 4);
                cp16(nb + woff, ks + part * 16);
                cp16(nb + TILE_B + woff, vs + part * 16);
            }
            asm volatile("cp.async.commit_group;" ::: "memory");
            asm volatile("cp.async.wait_group 1;" ::: "memory");
        } else {
            asm volatile("cp.async.wait_group 0;" ::: "memory");
        }
        __syncthreads();

        const uint32_t bufK = sb + (tl & 1) * BUF_B;
        const uint32_t bufV = bufK + TILE_B;

        // ---- S = Q K^T : B-frags via ldmatrix.x4 (two n-tiles per load) ----
        float s[8][4];
        #pragma unroll
        for (int i = 0; i < 8; ++i)
            #pragma unroll
            for (int j = 0; j < 4; ++j) s[i][j] = 0.f;

        #pragma unroll
        for (int kc2 = 0; kc2 < 4; ++kc2) {
            #pragma unroll
            for (int ntp = 0; ntp < 4; ++ntp) {
                uint32_t addr = bufK + (uint32_t)(ntp * 16 * 128) + krbase
                              + ((((uint32_t)(2 * kc2) + kcbit) ^ l7) << 4);
                uint32_t b0, b1, b2, b3;
                ldsm4(b0, b1, b2, b3, addr);
                mma_f16(s[2 * ntp],     qa[kc2], b0, b1);
                mma_f16(s[2 * ntp + 1], qa[kc2], b2, b3);
            }
        }

        // ---- fused softmax (f16x2 ex2) + HADD2 rsum + PV (ldmatrix.trans) ----
        __half2 hacc0, hacc1;
        #pragma unroll
        for (int kc2 = 0; kc2 < 4; ++kc2) {
            uint32_t pa[4];
            pa[0] = ex2h2(h2u(__floats2half2_rn(s[2 * kc2][0],     s[2 * kc2][1])));
            pa[1] = ex2h2(h2u(__floats2half2_rn(s[2 * kc2][2],     s[2 * kc2][3])));
            pa[2] = ex2h2(h2u(__floats2half2_rn(s[2 * kc2 + 1][0], s[2 * kc2 + 1][1])));
            pa[3] = ex2h2(h2u(__floats2half2_rn(s[2 * kc2 + 1][2], s[2 * kc2 + 1][3])));

            __half2 a0 = __hadd2(u2h(pa[0]), u2h(pa[2]));    // row g
            __half2 a1 = __hadd2(u2h(pa[1]), u2h(pa[3]));    // row g+8
            if (kc2 == 0) { hacc0 = a0; hacc1 = a1; }
            else          { hacc0 = __hadd2(hacc0, a0); hacc1 = __hadd2(hacc1, a1); }

            #pragma unroll
            for (int dtp = 0; dtp < 4; ++dtp) {
                uint32_t addr = bufV + (uint32_t)(kc2 * 16 * 128) + vrbase
                              + ((((uint32_t)(2 * dtp) + vcbit) ^ l7) << 4);
                uint32_t v0, v1, v2, v3;
                ldsm4t(v0, v1, v2, v3, addr);
                mma_f16(o[2 * dtp],     pa, v0, v1);
                mma_f16(o[2 * dtp + 1], pa, v2, v3);
            }
        }
        {
            float2 f0 = __half22float2(hacc0);
            float2 f1 = __half22float2(hacc1);
            rsum0 += f0.x + f0.y;
            rsum1 += f1.x + f1.y;
        }
        __syncthreads();
    }

    // ---- epilogue: quad-reduce row sums, normalize, store ----
    rsum0 += __shfl_xor_sync(0xffffffffu, rsum0, 1);
    rsum0 += __shfl_xor_sync(0xffffffffu, rsum0, 2);
    rsum1 += __shfl_xor_sync(0xffffffffu, rsum1, 1);
    rsum1 += __shfl_xor_sync(0xffffffffu, rsum1, 2);
    const float inv0 = 1.0f / rsum0;
    const float inv1 = 1.0f / rsum1;

    const size_t row0 = base + (size_t)(m0 + wrow + g) * HD;
    const size_t row1 = row0 + 8 * HD;
    #pragma unroll
    for (int dt = 0; dt < 8; ++dt) {
        float2 r0 = make_float2(o[dt][0] * inv0, o[dt][1] * inv0);
        float2 r1 = make_float2(o[dt][2] * inv1, o[dt][3] * inv1);
        *reinterpret_cast<float2*>(out + row0 + dt * 8 + 2 * t) = r0;
        *reinterpret_cast<float2*>(out + row1 + dt * 8 + 2 * t) = r1;
    }
}

extern "C" void kernel_launch(void* const* d_in, const int* in_sizes, int n_in,
                              void* d_out, int out_size)
{
    const float* q  = (const float*)d_in[0];
    const float* kp = (const float*)d_in[1];
    const float* kq = (const float*)d_in[2];
    const float* vp = (const float*)d_in[3];
    const float* vq = (const float*)d_in[4];
    float* out = (float*)d_out;

    static int cfg_done = 0;
    if (!cfg_done) {
        cudaFuncSetAttribute(tq_attn_mma,
                             cudaFuncAttributeMaxDynamicSharedMemorySize, SMEM_BYTES);
        cfg_done = 1;
    }

    deq_kv<<<(BH * SEQ * HD) / (8 * 256), 256>>>(kp, kq, vp, vq);

    dim3 grid(SEQ / BM, BH);
    tq_attn_mma<<<grid, NT, SMEM_BYTES>>>(q, out);
}